// round 5
// baseline (speedup 1.0000x reference)
#include <cuda_runtime.h>
#include <cstdint>

// Problem constants: input (64, 65536, 6) f32, output (64, 640) f32.
#define BATCHES     64
#define POINTS      65536
#define PAIRS       (POINTS / 2)            // 32768 pairs per batch
#define F4_PER_B    (POINTS * 6 / 4)        // 98304 float4 per batch
#define NUM_BINS    4
#define NUM_CELLS   64
#define STATS       10
#define FEAT        (NUM_CELLS * STATS)     // 640
#define WPC         5                       // packed u64 words per cell

// Kernel 1 (bbox) config
#define BPB1        32
#define T1          256
#define PAIRS_PER_BLK1 (PAIRS / BPB1)       // 1024
#define ITER1       (PAIRS_PER_BLK1 / T1)   // 4

// Kernel 2 (accumulate+finalize) config
#define BPB2        2                       // 2 x 64 = 128 blocks, 1/SM, single wave
#define T2          1024
#define PAIRS_PER_BLK2 (PAIRS / BPB2)       // 16384
#define ITER2       (PAIRS_PER_BLK2 / T2)   // 16
#define REPL        32                      // one replica per lane
#define HIST_U64    (NUM_CELLS * WPC * REPL)   // 10240 u64 = 80 KB
#define HIST_BYTES  (HIST_U64 * 8)

// Fixed-point packing constants.
// field = round(v*S) + bias, 22 bits used; magic-FFMA does the quantization.
#define S_PIC       2097152.0f              // 2^21 (pic in [0,1], no bias)
#define INV_S_PIC   (1.0f / 2097152.0f)
#define S_COV       16384.0f                // 2^14
#define INV_S_COV   (1.0f / 16384.0f)
#define BIAS_COV    1048576u                // 2^20 = 64*S_COV  (|cov| <= 64)
#define MAGIC       12582912.0f             // 1.5 * 2^23
#define MAGICB      13631488.0f             // MAGIC + BIAS_COV
#define FMASK       0x3FFFFFu               // low 22 mantissa bits

// Device scratch (zero at module load; restored to zero at end of each run).
__device__ unsigned int       g_bbox[BATCHES];
__device__ float              g_sums[BATCHES * FEAT];
__device__ unsigned int       g_cnt[BATCHES];

// ---------------------------------------------------------------------------
// Kernel 1: per-batch bbox_max = max(|pos|)
// Layout per point pair (12 floats = 3 float4):
//   a = [p0x p0y p0z o0x]  b = [o0y o0z p1x p1y]  c = [p1z o1x o1y o1z]
// ---------------------------------------------------------------------------
__global__ __launch_bounds__(T1) void k_bbox(const float4* __restrict__ in4) {
    const int batch = blockIdx.y;
    const int tid = threadIdx.x;
    const float4* p = in4 + (size_t)batch * F4_PER_B;
    const int base = blockIdx.x * PAIRS_PER_BLK1;

    float m = 0.0f;
#pragma unroll
    for (int k = 0; k < ITER1; k++) {
        int j = base + tid + k * T1;
        float4 a = p[3 * j + 0];
        float4 b = p[3 * j + 1];
        float4 c = p[3 * j + 2];
        m = fmaxf(m, fmaxf(fmaxf(fabsf(a.x), fabsf(a.y)), fabsf(a.z)));
        m = fmaxf(m, fmaxf(fmaxf(fabsf(b.z), fabsf(b.w)), fabsf(c.x)));
    }
#pragma unroll
    for (int o = 16; o > 0; o >>= 1)
        m = fmaxf(m, __shfl_xor_sync(0xFFFFFFFFu, m, o));

    __shared__ float sm[T1 / 32];
    if ((tid & 31) == 0) sm[tid >> 5] = m;
    __syncthreads();
    if (tid == 0) {
        float mm = sm[0];
#pragma unroll
        for (int i = 1; i < T1 / 32; i++) mm = fmaxf(mm, sm[i]);
        atomicMax(&g_bbox[batch], __float_as_uint(mm));  // positive floats
    }
}

// ---------------------------------------------------------------------------
// Kernel 2: bin + accumulate with 64-bit packed fixed-point smem atomics,
// then (last block per batch) finalize + L2-normalize + state reset.
//
// Packing per cell (5 u64 words, per-lane replica, addr = (cell*5+w)*32+lane):
//   w0: lo = count(+1)          hi = q(picx)            [no bias]
//   w1: lo = q(picy)            hi = q(picz)            [no bias]
//   w2: lo = q(ox*ox)+B         hi = q(ox*oy)+B
//   w3: lo = q(ox*oz)+B         hi = q(oy*oy)+B
//   w4: lo = q(oy*oz)+B         hi = q(oz*oz)+B
// Per (block,replica,cell) adds <= 1024 -> field sum < 2^31: no carry.
// ---------------------------------------------------------------------------
extern __shared__ unsigned long long hist[];   // HIST_U64

__device__ __forceinline__ unsigned int qpic(float v) {
    return __float_as_uint(fmaf(v, S_PIC, MAGIC)) & FMASK;
}
__device__ __forceinline__ unsigned int qcov(float a, float bS) {
    return __float_as_uint(fmaf(a, bS, MAGICB)) & FMASK;
}
__device__ __forceinline__ unsigned long long pk(unsigned int lo, unsigned int hi) {
    return (unsigned long long)lo | ((unsigned long long)hi << 32);
}

__device__ __forceinline__ void accum_point(
    unsigned long long* __restrict__ h,   // hist + lane
    float px, float py, float pz,
    float ox, float oy, float oz,
    float bbox, float inv)
{
    float picx = (px + bbox) * inv;
    float picy = (py + bbox) * inv;
    float picz = (pz + bbox) * inv;
    int ix = (int)(picx * 4.0f); ix = min(max(ix, 0), 3);
    int iy = (int)(picy * 4.0f); iy = min(max(iy, 0), 3);
    int iz = (int)(picz * 4.0f); iz = min(max(iz, 0), 3);
    int cell = (ix * NUM_BINS + iy) * NUM_BINS + iz;
    unsigned long long* d = h + cell * (WPC * REPL);

    float oxS = ox * S_COV;
    float oyS = oy * S_COV;
    float ozS = oz * S_COV;

    atomicAdd(d + 0 * REPL, pk(1u, qpic(picx)));
    atomicAdd(d + 1 * REPL, pk(qpic(picy), qpic(picz)));
    atomicAdd(d + 2 * REPL, pk(qcov(ox, oxS), qcov(oy, oxS)));
    atomicAdd(d + 3 * REPL, pk(qcov(oz, oxS), qcov(oy, oyS)));
    atomicAdd(d + 4 * REPL, pk(qcov(oz, oyS), qcov(oz, ozS)));
}

__global__ __launch_bounds__(T2) void k_accum(const float4* __restrict__ in4,
                                              float* __restrict__ out) {
    const int batch = blockIdx.y;
    const int tid = threadIdx.x;
    const int lane = tid & 31;

    // zero histogram (16B stores)
    float4* h4 = (float4*)hist;
#pragma unroll
    for (int i = tid; i < (int)(HIST_BYTES / 16); i += T2)
        h4[i] = make_float4(0.f, 0.f, 0.f, 0.f);
    __syncthreads();

    const float bbox = __uint_as_float(g_bbox[batch]);
    const float th = fmaxf(2.0f * bbox, 1e-5f);
    const float inv = 1.0f / th;

    const float4* p = in4 + (size_t)batch * F4_PER_B;
    const int base = blockIdx.x * PAIRS_PER_BLK2;
    unsigned long long* hrep = hist + lane;

#pragma unroll 2
    for (int k = 0; k < ITER2; k++) {
        int j = base + tid + k * T2;
        float4 a = p[3 * j + 0];
        float4 b = p[3 * j + 1];
        float4 c = p[3 * j + 2];
        accum_point(hrep, a.x, a.y, a.z, a.w, b.x, b.y, bbox, inv);
        accum_point(hrep, b.z, b.w, c.x, c.y, c.z, c.w, bbox, inv);
    }
    __syncthreads();

    // ---- decode & flush to g_sums ----
    __shared__ float cnt_s[NUM_CELLS];
    float* sums = g_sums + batch * FEAT;

    // phase A: w0 -> count + sum(picx)
    if (tid < NUM_CELLS) {
        const int cell = tid;
        unsigned long long lo = 0, hi = 0;
#pragma unroll
        for (int r = 0; r < REPL; r++) {
            unsigned long long w = hist[(cell * WPC + 0) * REPL + ((r + lane) & 31)];
            lo += (unsigned int)w;
            hi += (unsigned int)(w >> 32);
        }
        float cnt = (float)lo;                 // <= 32768, exact
        cnt_s[cell] = cnt;
        atomicAdd(&sums[cell * STATS + 0], cnt);
        atomicAdd(&sums[cell * STATS + 1], (float)(long long)hi * INV_S_PIC);
    }
    __syncthreads();

    // phase B: w1..w4 -> remaining 8 stats
    if (tid < NUM_CELLS * 4) {
        const int cell = tid >> 2;
        const int pair = (tid & 3) + 1;        // 1..4
        unsigned long long lo = 0, hi = 0;
#pragma unroll
        for (int r = 0; r < REPL; r++) {
            unsigned long long w = hist[(cell * WPC + pair) * REPL + ((r + lane) & 31)];
            lo += (unsigned int)w;
            hi += (unsigned int)(w >> 32);
        }
        float v0, v1; int s0, s1;
        if (pair == 1) {
            v0 = (float)(long long)lo * INV_S_PIC;
            v1 = (float)(long long)hi * INV_S_PIC;
            s0 = 2; s1 = 3;
        } else {
            unsigned long long bias =
                (unsigned long long)(unsigned int)cnt_s[cell] * (unsigned long long)BIAS_COV;
            v0 = (float)(long long)(lo - bias) * INV_S_COV;
            v1 = (float)(long long)(hi - bias) * INV_S_COV;
            s0 = 4 + (pair - 2) * 2; s1 = s0 + 1;
        }
        atomicAdd(&sums[cell * STATS + s0], v0);
        atomicAdd(&sums[cell * STATS + s1], v1);
    }

    // ---- last block of this batch finalizes ----
    __shared__ unsigned int s_old;
    __syncthreads();
    if (tid == 0) {
        __threadfence();
        s_old = atomicAdd(&g_cnt[batch], 1u);
    }
    __syncthreads();
    if (s_old != BPB2 - 1) return;
    __threadfence();   // acquire: see the other block's g_sums additions

    // finalize (threads 0..639 active; all 1024 join barriers)
    __shared__ float wsum[FEAT / 32];
    __shared__ float s_inv;
    float f = 0.0f;
    if (tid < FEAT) {
        const int cell = tid / STATS;
        const int s = tid - cell * STATS;
        float cnt = sums[cell * STATS];
        float val = sums[tid];
        float fc = fmaxf(cnt, 1.0f);
        float up = rsqrtf(fc);
        if (s == 0) {
            f = 0.001f * cnt * up;
        } else if (s < 4) {
            int d = s - 1;
            int ci = (d == 0) ? (cell >> 4) : (d == 1) ? ((cell >> 2) & 3) : (cell & 3);
            float g = ((float)ci + 0.5f) * 0.25f;
            f = (val - cnt * g) * up;
        } else {
            f = val / fc;
        }
    }
    float q = f * f;
#pragma unroll
    for (int o = 16; o > 0; o >>= 1)
        q += __shfl_xor_sync(0xFFFFFFFFu, q, o);
    if ((tid & 31) == 0 && tid < FEAT) wsum[tid >> 5] = q;
    __syncthreads();

    // reset state for the next replay
    if (tid < FEAT) sums[tid] = 0.0f;
    if (tid == 0) {
        g_bbox[batch] = 0u;
        g_cnt[batch] = 0u;
        float ss = 0.0f;
#pragma unroll
        for (int i = 0; i < FEAT / 32; i++) ss += wsum[i];
        s_inv = 1.0f / fmaxf(sqrtf(ss), 1e-12f);
    }
    __syncthreads();
    if (tid < FEAT) out[batch * FEAT + tid] = f * s_inv;
}

// ---------------------------------------------------------------------------
extern "C" void kernel_launch(void* const* d_in, const int* in_sizes, int n_in,
                              void* d_out, int out_size) {
    const float4* in4 = (const float4*)d_in[0];
    float* out = (float*)d_out;
    (void)in_sizes; (void)n_in; (void)out_size;

    cudaFuncSetAttribute(k_accum, cudaFuncAttributeMaxDynamicSharedMemorySize,
                         HIST_BYTES);

    k_bbox<<<dim3(BPB1, BATCHES), T1>>>(in4);
    k_accum<<<dim3(BPB2, BATCHES), T2, HIST_BYTES>>>(in4, out);
}